// round 5
// baseline (speedup 1.0000x reference)
#include <cuda_runtime.h>
#include <cuda_fp16.h>
#include <math.h>

#define NN 100000
#define FD 500
#define NC 64
#define KH 10
#define EMAX 3200000
#define EPAD (EMAX + 32 * NN)      // worst-case padded CSR
#define NB_SCAN ((NN + 1023) / 1024)

// ---- scratch (no allocations allowed) ----
__device__ __half2 g_yA[(size_t)(NN + 1) * 32]; // ping (+1 sentinel zero row)
__device__ __half2 g_yB[(size_t)(NN + 1) * 32]; // pong
__device__ float g_hidden[(size_t)NN * NC];     // scaled PPR accumulator (fp32)
__device__ float g_dinv[NN];
__device__ float g_sdeg[NN];
__device__ int   g_cnt[NN];
__device__ int   g_cursor[NN];
__device__ int   g_off[NN + 1];
__device__ int   g_bsum[NB_SCAN];
__device__ int   g_src[EPAD];

// ---------------- in-degree count ----------------
__global__ void cnt_zero_kernel() {
    int i = blockIdx.x * blockDim.x + threadIdx.x;
    if (i < NN) g_cnt[i] = 0;
}

__global__ void cnt_acc_kernel(const int* __restrict__ col, int E) {
    int e = blockIdx.x * blockDim.x + threadIdx.x;
    if (e < E) atomicAdd(&g_cnt[col[e]], 1);
}

// ---------------- scan over PADDED counts + dinv/sdeg/cursor ----------------
__global__ __launch_bounds__(1024) void scan1_kernel() {
    __shared__ int sh[1024];
    int i = blockIdx.x * 1024 + threadIdx.x;
    int c = (i < NN) ? g_cnt[i] : 0;
    int v = (c + 31) & ~31;                    // padded to multiple of 32
    sh[threadIdx.x] = v;
    __syncthreads();
#pragma unroll
    for (int off = 1; off < 1024; off <<= 1) {
        int t = 0;
        if (threadIdx.x >= off) t = sh[threadIdx.x - off];
        __syncthreads();
        if (threadIdx.x >= off) sh[threadIdx.x] += t;
        __syncthreads();
    }
    if (i < NN) {
        g_off[i] = sh[threadIdx.x] - v;        // exclusive, block-local (padded)
        float deg = (float)(c + 1);            // + self loop (real degree)
        g_dinv[i] = rsqrtf(deg);
        g_sdeg[i] = sqrtf(deg);
        g_cursor[i] = 0;
    }
    if (threadIdx.x == 1023) g_bsum[blockIdx.x] = sh[1023];
}

__global__ void scan2_kernel() {
    if (threadIdx.x == 0 && blockIdx.x == 0) {
        int running = 0;
        for (int b = 0; b < NB_SCAN; b++) {
            int t = g_bsum[b];
            g_bsum[b] = running;
            running += t;
        }
        g_off[NN] = running;
    }
}

__global__ __launch_bounds__(1024) void scan3_kernel() {
    int i = blockIdx.x * 1024 + threadIdx.x;
    if (i < NN) g_off[i] += g_bsum[blockIdx.x];
}

// ---------------- CSR fill ----------------
__global__ void fill_kernel(const int* __restrict__ row, const int* __restrict__ col, int E) {
    int e = blockIdx.x * blockDim.x + threadIdx.x;
    if (e < E) {
        int c = col[e];
        int p = atomicAdd(&g_cursor[c], 1);
        g_src[g_off[c] + p] = row[e];
    }
}

// pad remaining slots with sentinel NN; also zero sentinel y rows
__global__ void pad_kernel() {
    int i = blockIdx.x * blockDim.x + threadIdx.x;
    if (i < 32) {
        g_yA[(size_t)NN * 32 + i] = __float2half2_rn(0.0f);
        g_yB[(size_t)NN * 32 + i] = __float2half2_rn(0.0f);
    }
    if (i < NN) {
        int beg = g_off[i] + g_cursor[i];
        int end = g_off[i + 1];
        for (int p = beg; p < end; p++) g_src[p] = NN;
    }
}

// ---------------- fused MLP: y0 = dinv*(relu(x@W1+b1)@W2 + b2) ----------------
__global__ __launch_bounds__(256) void mlp_kernel(
    const float* __restrict__ x,
    const float* __restrict__ W1, const float* __restrict__ b1,
    const float* __restrict__ W2, const float* __restrict__ b2,
    const float* __restrict__ temp)
{
    __shared__ float As[8][68];
    __shared__ float Bs[8][68];
    __shared__ float Hs[64][65];
    __shared__ float W2s[64][64];
    __shared__ float bias2[64];

    const int t = threadIdx.x;
    const int row0 = blockIdx.x * 64;
    const int ty = t >> 4;
    const int tx = t & 15;

    for (int i = t; i < 64 * 64; i += 256) W2s[i >> 6][i & 63] = W2[i];
    if (t < 64) bias2[t] = b2[t];

    float acc[4][4];
#pragma unroll
    for (int i = 0; i < 4; i++)
#pragma unroll
        for (int j = 0; j < 4; j++) acc[i][j] = 0.0f;

    const int lm = t >> 2;
    const int lq = t & 3;

    for (int k0 = 0; k0 < FD; k0 += 8) {
        {
            int gr = row0 + lm;
            int gk = k0 + lq * 2;
            float2 xv = make_float2(0.0f, 0.0f);
            if (gr < NN && gk + 1 < FD) {
                xv = *reinterpret_cast<const float2*>(&x[(size_t)gr * FD + gk]);
            } else if (gr < NN && gk < FD) {
                xv.x = x[(size_t)gr * FD + gk];
            }
            As[lq * 2 + 0][lm] = xv.x;
            As[lq * 2 + 1][lm] = xv.y;
        }
        {
#pragma unroll
            for (int j = 0; j < 2; j++) {
                int idx = t + j * 256;
                int n = idx & 63, kl = idx >> 6;
                int gk = k0 + kl;
                Bs[kl][n] = (gk < FD) ? W1[gk * 64 + n] : 0.0f;
            }
        }
        __syncthreads();

#pragma unroll
        for (int kl = 0; kl < 8; kl++) {
            float4 a = *reinterpret_cast<const float4*>(&As[kl][ty * 4]);
            float4 b = *reinterpret_cast<const float4*>(&Bs[kl][tx * 4]);
            float av[4] = {a.x, a.y, a.z, a.w};
            float bv[4] = {b.x, b.y, b.z, b.w};
#pragma unroll
            for (int i = 0; i < 4; i++)
#pragma unroll
                for (int j = 0; j < 4; j++) acc[i][j] += av[i] * bv[j];
        }
        __syncthreads();
    }

    float bb[4];
#pragma unroll
    for (int j = 0; j < 4; j++) bb[j] = b1[tx * 4 + j];
#pragma unroll
    for (int i = 0; i < 4; i++)
#pragma unroll
        for (int j = 0; j < 4; j++) {
            float v = acc[i][j] + bb[j];
            Hs[ty * 4 + i][tx * 4 + j] = v > 0.0f ? v : 0.0f;
        }
    __syncthreads();

    float acc2[4][4];
#pragma unroll
    for (int i = 0; i < 4; i++)
#pragma unroll
        for (int j = 0; j < 4; j++) acc2[i][j] = 0.0f;

#pragma unroll 8
    for (int k = 0; k < 64; k++) {
        float av[4], bv[4];
        float4 b = *reinterpret_cast<const float4*>(&W2s[k][tx * 4]);
        bv[0] = b.x; bv[1] = b.y; bv[2] = b.z; bv[3] = b.w;
#pragma unroll
        for (int i = 0; i < 4; i++) av[i] = Hs[ty * 4 + i][k];
#pragma unroll
        for (int i = 0; i < 4; i++)
#pragma unroll
            for (int j = 0; j < 4; j++) acc2[i][j] += av[i] * bv[j];
    }

    float t0 = temp[0];
#pragma unroll
    for (int i = 0; i < 4; i++) {
        int gr = row0 + ty * 4 + i;
        if (gr < NN) {
            float d = g_dinv[gr];
            float4 v;
            v.x = d * (acc2[i][0] + bias2[tx * 4 + 0]);
            v.y = d * (acc2[i][1] + bias2[tx * 4 + 1]);
            v.z = d * (acc2[i][2] + bias2[tx * 4 + 2]);
            v.w = d * (acc2[i][3] + bias2[tx * 4 + 3]);
            g_yA[(size_t)gr * 32 + tx * 2 + 0] = __floats2half2_rn(v.x, v.y);
            g_yA[(size_t)gr * 32 + tx * 2 + 1] = __floats2half2_rn(v.z, v.w);
            float4 h = make_float4(t0 * v.x, t0 * v.y, t0 * v.z, t0 * v.w);
            *reinterpret_cast<float4*>(&g_hidden[(size_t)gr * NC + tx * 4]) = h;
        }
    }
}

// ---------------- pull propagation: warp per node, padded CSR, single unrolled path ----------------
__global__ __launch_bounds__(256) void propagate_kernel(const float* __restrict__ temp, int k, int flip) {
    const __half2* __restrict__ y = flip ? g_yB : g_yA;
    __half2* __restrict__ yn = flip ? g_yA : g_yB;
    int node = (blockIdx.x * blockDim.x + threadIdx.x) >> 5;
    int lane = threadIdx.x & 31;
    if (node >= NN) return;

    float d = g_dinv[node];
    size_t base2 = (size_t)node * 32 + lane;
    float2 self = __half22float2(y[base2]);
    float ax = self.x, ay = self.y;   // self-loop term: + y_k[c]

    int beg = g_off[node];
    int end = g_off[node + 1];       // end-beg is a multiple of 32
    for (int i = beg; i < end; i += 32) {
        int s = __ldg(&g_src[i + lane]);
#pragma unroll
        for (int j = 0; j < 32; j++) {
            int sj = __shfl_sync(0xFFFFFFFFu, s, j);
            float2 v = __half22float2(__ldg(&y[(size_t)sj * 32 + lane]));
            ax += v.x;
            ay += v.y;
        }
    }

    float d2 = d * d;
    float ox = d2 * ax, oy = d2 * ay;
    yn[base2] = __floats2half2_rn(ox, oy);

    float tk = temp[k + 1];
    float2 h = *reinterpret_cast<float2*>(&g_hidden[(size_t)node * NC + lane * 2]);
    h.x += tk * ox;
    h.y += tk * oy;
    *reinterpret_cast<float2*>(&g_hidden[(size_t)node * NC + lane * 2]) = h;
}

// ---------------- final: out = log_softmax(hs * sqrt(deg)) ----------------
__global__ void final_kernel(float* __restrict__ out) {
    int warp = (blockIdx.x * blockDim.x + threadIdx.x) >> 5;
    int lane = threadIdx.x & 31;
    if (warp >= NN) return;
    float sd = g_sdeg[warp];
    size_t base = (size_t)warp * NC;
    float a = g_hidden[base + lane] * sd;
    float b = g_hidden[base + 32 + lane] * sd;
    float mx = fmaxf(a, b);
#pragma unroll
    for (int off = 16; off > 0; off >>= 1)
        mx = fmaxf(mx, __shfl_xor_sync(0xFFFFFFFFu, mx, off));
    float s = expf(a - mx) + expf(b - mx);
#pragma unroll
    for (int off = 16; off > 0; off >>= 1)
        s += __shfl_xor_sync(0xFFFFFFFFu, s, off);
    float l = mx + logf(s);
    out[base + lane] = a - l;
    out[base + 32 + lane] = b - l;
}

// ---------------- launch ----------------
extern "C" void kernel_launch(void* const* d_in, const int* in_sizes, int n_in,
                              void* d_out, int out_size)
{
    const float* x    = (const float*)d_in[0];
    const int*   ei   = (const int*)d_in[1];
    const float* W1   = (const float*)d_in[2];
    const float* b1   = (const float*)d_in[3];
    const float* W2   = (const float*)d_in[4];
    const float* b2   = (const float*)d_in[5];
    const float* temp = (const float*)d_in[6];
    float* out = (float*)d_out;

    const int E = in_sizes[1] / 2;
    const int* row = ei;       // source
    const int* col = ei + E;   // target

    // CSR build (padded to multiples of 32 per node)
    cnt_zero_kernel<<<(NN + 255) / 256, 256>>>();
    cnt_acc_kernel<<<(E + 255) / 256, 256>>>(col, E);
    scan1_kernel<<<NB_SCAN, 1024>>>();
    scan2_kernel<<<1, 32>>>();
    scan3_kernel<<<NB_SCAN, 1024>>>();
    fill_kernel<<<(E + 255) / 256, 256>>>(row, col, E);
    pad_kernel<<<(NN + 255) / 256, 256>>>();

    // MLP -> y0 in g_yA (fp16), hs init in g_hidden (fp32)
    mlp_kernel<<<(NN + 63) / 64, 256>>>(x, W1, b1, W2, b2, temp);

    // pull propagation: 1 warp per node
    int pblocks = (NN * 32 + 255) / 256;
    for (int k = 0; k < KH; k++) {
        propagate_kernel<<<pblocks, 256>>>(temp, k, k & 1);
    }

    final_kernel<<<(NN * 32 + 255) / 256, 256>>>(out);
}

// round 6
// speedup vs baseline: 1.0748x; 1.0748x over previous
#include <cuda_runtime.h>
#include <cuda_fp16.h>
#include <math.h>

#define NN 100000
#define FD 500
#define NC 64
#define KH 10
#define EMAX 3200000
#define EPAD (EMAX + 4 * NN)       // padded-to-4 CSR worst case
#define NB_SCAN ((NN + 1023) / 1024)

// ---- scratch (no allocations allowed) ----
__device__ __half2 g_yA[(size_t)(NN + 1) * 32]; // ping (+1 sentinel zero row)
__device__ __half2 g_yB[(size_t)(NN + 1) * 32]; // pong
__device__ float g_hidden[(size_t)NN * NC];     // scaled PPR accumulator (fp32)
__device__ float g_dinv[NN];
__device__ float g_sdeg[NN];
__device__ int   g_cnt[NN];
__device__ int   g_cursor[NN];
__device__ int   g_off[NN + 1];
__device__ int   g_bsum[NB_SCAN];
__device__ int   g_src[EPAD];

// ---------------- in-degree count ----------------
__global__ void cnt_zero_kernel() {
    int i = blockIdx.x * blockDim.x + threadIdx.x;
    if (i < NN) g_cnt[i] = 0;
}

__global__ void cnt_acc_kernel(const int* __restrict__ col, int E) {
    int e = blockIdx.x * blockDim.x + threadIdx.x;
    if (e < E) atomicAdd(&g_cnt[col[e]], 1);
}

// dinv/sdeg straight from counts (so MLP can run early, at ncu capture slot 3)
__global__ void dinv_kernel() {
    int i = blockIdx.x * blockDim.x + threadIdx.x;
    if (i < NN) {
        float deg = (float)(g_cnt[i] + 1);   // + self loop
        g_dinv[i] = rsqrtf(deg);
        g_sdeg[i] = sqrtf(deg);
        g_cursor[i] = 0;
    }
}

// ---------------- scan over counts padded to multiple of 4 ----------------
__global__ __launch_bounds__(1024) void scan1_kernel() {
    __shared__ int sh[1024];
    int i = blockIdx.x * 1024 + threadIdx.x;
    int c = (i < NN) ? g_cnt[i] : 0;
    int v = (c + 3) & ~3;                      // pad to multiple of 4
    sh[threadIdx.x] = v;
    __syncthreads();
#pragma unroll
    for (int off = 1; off < 1024; off <<= 1) {
        int t = 0;
        if (threadIdx.x >= off) t = sh[threadIdx.x - off];
        __syncthreads();
        if (threadIdx.x >= off) sh[threadIdx.x] += t;
        __syncthreads();
    }
    if (i < NN) g_off[i] = sh[threadIdx.x] - v;
    if (threadIdx.x == 1023) g_bsum[blockIdx.x] = sh[1023];
}

__global__ void scan2_kernel() {
    if (threadIdx.x == 0 && blockIdx.x == 0) {
        int running = 0;
        for (int b = 0; b < NB_SCAN; b++) {
            int t = g_bsum[b];
            g_bsum[b] = running;
            running += t;
        }
        g_off[NN] = running;
    }
}

__global__ __launch_bounds__(1024) void scan3_kernel() {
    int i = blockIdx.x * 1024 + threadIdx.x;
    if (i < NN) g_off[i] += g_bsum[blockIdx.x];
}

// ---------------- CSR fill ----------------
__global__ void fill_kernel(const int* __restrict__ row, const int* __restrict__ col, int E) {
    int e = blockIdx.x * blockDim.x + threadIdx.x;
    if (e < E) {
        int c = col[e];
        int p = atomicAdd(&g_cursor[c], 1);
        g_src[g_off[c] + p] = row[e];
    }
}

// pad remaining (<=3 per node) slots with sentinel NN; zero sentinel y rows
__global__ void pad_kernel() {
    int i = blockIdx.x * blockDim.x + threadIdx.x;
    if (i < 32) {
        g_yA[(size_t)NN * 32 + i] = __float2half2_rn(0.0f);
        g_yB[(size_t)NN * 32 + i] = __float2half2_rn(0.0f);
    }
    if (i < NN) {
        int beg = g_off[i] + g_cursor[i];
        int end = g_off[i + 1];
        for (int p = beg; p < end; p++) g_src[p] = NN;
    }
}

// ---------------- fused MLP: y0 = dinv*(relu(x@W1+b1)@W2 + b2) ----------------
__global__ __launch_bounds__(256) void mlp_kernel(
    const float* __restrict__ x,
    const float* __restrict__ W1, const float* __restrict__ b1,
    const float* __restrict__ W2, const float* __restrict__ b2,
    const float* __restrict__ temp)
{
    __shared__ float As[8][68];
    __shared__ float Bs[8][68];
    __shared__ float Hs[64][65];
    __shared__ float W2s[64][64];
    __shared__ float bias2[64];

    const int t = threadIdx.x;
    const int row0 = blockIdx.x * 64;
    const int ty = t >> 4;
    const int tx = t & 15;

    for (int i = t; i < 64 * 64; i += 256) W2s[i >> 6][i & 63] = W2[i];
    if (t < 64) bias2[t] = b2[t];

    float acc[4][4];
#pragma unroll
    for (int i = 0; i < 4; i++)
#pragma unroll
        for (int j = 0; j < 4; j++) acc[i][j] = 0.0f;

    const int lm = t >> 2;
    const int lq = t & 3;

    for (int k0 = 0; k0 < FD; k0 += 8) {
        {
            int gr = row0 + lm;
            int gk = k0 + lq * 2;
            float2 xv = make_float2(0.0f, 0.0f);
            if (gr < NN && gk + 1 < FD) {
                xv = *reinterpret_cast<const float2*>(&x[(size_t)gr * FD + gk]);
            } else if (gr < NN && gk < FD) {
                xv.x = x[(size_t)gr * FD + gk];
            }
            As[lq * 2 + 0][lm] = xv.x;
            As[lq * 2 + 1][lm] = xv.y;
        }
        {
#pragma unroll
            for (int j = 0; j < 2; j++) {
                int idx = t + j * 256;
                int n = idx & 63, kl = idx >> 6;
                int gk = k0 + kl;
                Bs[kl][n] = (gk < FD) ? W1[gk * 64 + n] : 0.0f;
            }
        }
        __syncthreads();

#pragma unroll
        for (int kl = 0; kl < 8; kl++) {
            float4 a = *reinterpret_cast<const float4*>(&As[kl][ty * 4]);
            float4 b = *reinterpret_cast<const float4*>(&Bs[kl][tx * 4]);
            float av[4] = {a.x, a.y, a.z, a.w};
            float bv[4] = {b.x, b.y, b.z, b.w};
#pragma unroll
            for (int i = 0; i < 4; i++)
#pragma unroll
                for (int j = 0; j < 4; j++) acc[i][j] += av[i] * bv[j];
        }
        __syncthreads();
    }

    float bb[4];
#pragma unroll
    for (int j = 0; j < 4; j++) bb[j] = b1[tx * 4 + j];
#pragma unroll
    for (int i = 0; i < 4; i++)
#pragma unroll
        for (int j = 0; j < 4; j++) {
            float v = acc[i][j] + bb[j];
            Hs[ty * 4 + i][tx * 4 + j] = v > 0.0f ? v : 0.0f;
        }
    __syncthreads();

    float acc2[4][4];
#pragma unroll
    for (int i = 0; i < 4; i++)
#pragma unroll
        for (int j = 0; j < 4; j++) acc2[i][j] = 0.0f;

#pragma unroll 8
    for (int k = 0; k < 64; k++) {
        float av[4], bv[4];
        float4 b = *reinterpret_cast<const float4*>(&W2s[k][tx * 4]);
        bv[0] = b.x; bv[1] = b.y; bv[2] = b.z; bv[3] = b.w;
#pragma unroll
        for (int i = 0; i < 4; i++) av[i] = Hs[ty * 4 + i][k];
#pragma unroll
        for (int i = 0; i < 4; i++)
#pragma unroll
            for (int j = 0; j < 4; j++) acc2[i][j] += av[i] * bv[j];
    }

    float t0 = temp[0];
#pragma unroll
    for (int i = 0; i < 4; i++) {
        int gr = row0 + ty * 4 + i;
        if (gr < NN) {
            float d = g_dinv[gr];
            float4 v;
            v.x = d * (acc2[i][0] + bias2[tx * 4 + 0]);
            v.y = d * (acc2[i][1] + bias2[tx * 4 + 1]);
            v.z = d * (acc2[i][2] + bias2[tx * 4 + 2]);
            v.w = d * (acc2[i][3] + bias2[tx * 4 + 3]);
            g_yA[(size_t)gr * 32 + tx * 2 + 0] = __floats2half2_rn(v.x, v.y);
            g_yA[(size_t)gr * 32 + tx * 2 + 1] = __floats2half2_rn(v.z, v.w);
            float4 h = make_float4(t0 * v.x, t0 * v.y, t0 * v.z, t0 * v.w);
            *reinterpret_cast<float4*>(&g_hidden[(size_t)gr * NC + tx * 4]) = h;
        }
    }
}

// ---------------- pull propagation: warp per node, 4 edges per LDG.128 ----------------
// lane layout: jsub = lane>>3 (edge subgroup 0..3), c = lane&7 (uint4 chunk of row)
__device__ __forceinline__ void acc_uint4(float acc[8], uint4 v) {
    __half2 h[4];
    *reinterpret_cast<uint4*>(h) = v;
#pragma unroll
    for (int t = 0; t < 4; t++) {
        float2 f = __half22float2(h[t]);
        acc[2 * t + 0] += f.x;
        acc[2 * t + 1] += f.y;
    }
}

__global__ __launch_bounds__(256) void propagate_kernel(const float* __restrict__ temp, int k, int flip) {
    const __half2* __restrict__ y = flip ? g_yB : g_yA;
    __half2* __restrict__ yn = flip ? g_yA : g_yB;
    int node = (blockIdx.x * blockDim.x + threadIdx.x) >> 5;
    int lane = threadIdx.x & 31;
    if (node >= NN) return;
    const int jsub = lane >> 3;
    const int c = lane & 7;

    float acc[8];
#pragma unroll
    for (int q = 0; q < 8; q++) acc[q] = 0.0f;

    int beg = g_off[node];
    int end = g_off[node + 1];   // end-beg is a multiple of 4

    int i = beg;
    // full 32-edge chunks: static unroll-8, 8 independent LDG.128 in flight
    for (; i + 32 <= end; i += 32) {
        int s = __ldg(&g_src[i + lane]);
#pragma unroll
        for (int t = 0; t < 8; t++) {
            int sj = __shfl_sync(0xFFFFFFFFu, s, t * 4 + jsub);
            uint4 v = __ldg(reinterpret_cast<const uint4*>(y + (size_t)sj * 32) + c);
            acc_uint4(acc, v);
        }
    }
    // tail: < 32 edges, multiple of 4
    if (i < end) {
        int n = end - i;
        int s = (lane < n) ? __ldg(&g_src[i + lane]) : NN;
        for (int t = 0; t * 4 < n; t++) {
            int sj = __shfl_sync(0xFFFFFFFFu, s, t * 4 + jsub);
            uint4 v = __ldg(reinterpret_cast<const uint4*>(y + (size_t)sj * 32) + c);
            acc_uint4(acc, v);
        }
    }

    // reduce the 4 edge subgroups (lanes c, c+8, c+16, c+24)
#pragma unroll
    for (int q = 0; q < 8; q++) {
        acc[q] += __shfl_xor_sync(0xFFFFFFFFu, acc[q], 8);
        acc[q] += __shfl_xor_sync(0xFFFFFFFFu, acc[q], 16);
    }

    // self-loop term: + y_k[c] (same chunk layout)
    {
        uint4 sv = __ldg(reinterpret_cast<const uint4*>(y + (size_t)node * 32) + c);
        acc_uint4(acc, sv);
    }

    float d = g_dinv[node];
    float d2 = d * d;
    float o[8];
#pragma unroll
    for (int q = 0; q < 8; q++) o[q] = d2 * acc[q];

    // writers (values replicated across jsub groups)
    if (jsub == 0) {
        __half2 h[4];
#pragma unroll
        for (int t = 0; t < 4; t++) h[t] = __floats2half2_rn(o[2 * t], o[2 * t + 1]);
        *(reinterpret_cast<uint4*>(yn + (size_t)node * 32) + c) = *reinterpret_cast<uint4*>(h);
    } else if (jsub == 1) {
        float tk = temp[k + 1];
        float4* hp = reinterpret_cast<float4*>(g_hidden + (size_t)node * NC) + c * 2;
        float4 hv = *hp;
        hv.x += tk * o[0]; hv.y += tk * o[1]; hv.z += tk * o[2]; hv.w += tk * o[3];
        *hp = hv;
    } else if (jsub == 2) {
        float tk = temp[k + 1];
        float4* hp = reinterpret_cast<float4*>(g_hidden + (size_t)node * NC) + c * 2 + 1;
        float4 hv = *hp;
        hv.x += tk * o[4]; hv.y += tk * o[5]; hv.z += tk * o[6]; hv.w += tk * o[7];
        *hp = hv;
    }
}

// ---------------- final: out = log_softmax(hs * sqrt(deg)) ----------------
__global__ void final_kernel(float* __restrict__ out) {
    int warp = (blockIdx.x * blockDim.x + threadIdx.x) >> 5;
    int lane = threadIdx.x & 31;
    if (warp >= NN) return;
    float sd = g_sdeg[warp];
    size_t base = (size_t)warp * NC;
    float a = g_hidden[base + lane] * sd;
    float b = g_hidden[base + 32 + lane] * sd;
    float mx = fmaxf(a, b);
#pragma unroll
    for (int off = 16; off > 0; off >>= 1)
        mx = fmaxf(mx, __shfl_xor_sync(0xFFFFFFFFu, mx, off));
    float s = expf(a - mx) + expf(b - mx);
#pragma unroll
    for (int off = 16; off > 0; off >>= 1)
        s += __shfl_xor_sync(0xFFFFFFFFu, s, off);
    float l = mx + logf(s);
    out[base + lane] = a - l;
    out[base + 32 + lane] = b - l;
}

// ---------------- launch ----------------
extern "C" void kernel_launch(void* const* d_in, const int* in_sizes, int n_in,
                              void* d_out, int out_size)
{
    const float* x    = (const float*)d_in[0];
    const int*   ei   = (const int*)d_in[1];
    const float* W1   = (const float*)d_in[2];
    const float* b1   = (const float*)d_in[3];
    const float* W2   = (const float*)d_in[4];
    const float* b2   = (const float*)d_in[5];
    const float* temp = (const float*)d_in[6];
    float* out = (float*)d_out;

    const int E = in_sizes[1] / 2;
    const int* row = ei;       // source
    const int* col = ei + E;   // target

    // launches 0..2, then MLP at index 3 (ncu capture slot)
    cnt_zero_kernel<<<(NN + 255) / 256, 256>>>();
    cnt_acc_kernel<<<(E + 255) / 256, 256>>>(col, E);
    dinv_kernel<<<(NN + 255) / 256, 256>>>();
    mlp_kernel<<<(NN + 63) / 64, 256>>>(x, W1, b1, W2, b2, temp);

    // CSR build (padded to multiple of 4 per node)
    scan1_kernel<<<NB_SCAN, 1024>>>();
    scan2_kernel<<<1, 32>>>();
    scan3_kernel<<<NB_SCAN, 1024>>>();
    fill_kernel<<<(E + 255) / 256, 256>>>(row, col, E);
    pad_kernel<<<(NN + 255) / 256, 256>>>();

    // pull propagation: 1 warp per node
    int pblocks = (NN * 32 + 255) / 256;
    for (int k = 0; k < KH; k++) {
        propagate_kernel<<<pblocks, 256>>>(temp, k, k & 1);
    }

    final_kernel<<<(NN * 32 + 255) / 256, 256>>>(out);
}

// round 7
// speedup vs baseline: 1.3821x; 1.2859x over previous
#include <cuda_runtime.h>
#include <cuda_fp16.h>
#include <math.h>

#define NN 100000
#define FD 500
#define NC 64
#define KH 10
#define EMAX 3200000
#define NB_SCAN ((NN + 1023) / 1024)

// ---- scratch (no allocations allowed) ----
__device__ __half2 g_yA[(size_t)(NN + 1) * 32]; // ping
__device__ __half2 g_yB[(size_t)(NN + 1) * 32]; // pong
__device__ float g_hidden[(size_t)NN * NC];     // scaled PPR accumulator (fp32)
__device__ float g_dinv[NN];
__device__ float g_sdeg[NN];
__device__ int   g_cnt[NN];
__device__ int   g_cursor[NN];
__device__ int   g_off[NN + 1];
__device__ int   g_bsum[NB_SCAN];
__device__ int   g_src[EMAX];

// ---------------- in-degree count ----------------
__global__ void cnt_zero_kernel() {
    int i = blockIdx.x * blockDim.x + threadIdx.x;
    if (i < NN) g_cnt[i] = 0;
}

__global__ void cnt_acc_kernel(const int* __restrict__ col, int E) {
    int e = blockIdx.x * blockDim.x + threadIdx.x;
    if (e < E) atomicAdd(&g_cnt[col[e]], 1);
}

// dinv/sdeg from counts (runs before mlp so mlp sits at ncu capture slot 3)
__global__ void dinv_kernel() {
    int i = blockIdx.x * blockDim.x + threadIdx.x;
    if (i < NN) {
        float deg = (float)(g_cnt[i] + 1);   // + self loop
        g_dinv[i] = rsqrtf(deg);
        g_sdeg[i] = sqrtf(deg);
        g_cursor[i] = 0;
    }
}

// ---------------- scan ----------------
__global__ __launch_bounds__(1024) void scan1_kernel() {
    __shared__ int sh[1024];
    int i = blockIdx.x * 1024 + threadIdx.x;
    int v = (i < NN) ? g_cnt[i] : 0;
    sh[threadIdx.x] = v;
    __syncthreads();
#pragma unroll
    for (int off = 1; off < 1024; off <<= 1) {
        int t = 0;
        if (threadIdx.x >= off) t = sh[threadIdx.x - off];
        __syncthreads();
        if (threadIdx.x >= off) sh[threadIdx.x] += t;
        __syncthreads();
    }
    if (i < NN) g_off[i] = sh[threadIdx.x] - v;
    if (threadIdx.x == 1023) g_bsum[blockIdx.x] = sh[1023];
}

__global__ void scan2_kernel() {
    if (threadIdx.x == 0 && blockIdx.x == 0) {
        int running = 0;
        for (int b = 0; b < NB_SCAN; b++) {
            int t = g_bsum[b];
            g_bsum[b] = running;
            running += t;
        }
        g_off[NN] = running;
    }
}

__global__ __launch_bounds__(1024) void scan3_kernel() {
    int i = blockIdx.x * 1024 + threadIdx.x;
    if (i < NN) g_off[i] += g_bsum[blockIdx.x];
}

// ---------------- CSR fill ----------------
__global__ void fill_kernel(const int* __restrict__ row, const int* __restrict__ col, int E) {
    int e = blockIdx.x * blockDim.x + threadIdx.x;
    if (e < E) {
        int c = col[e];
        int p = atomicAdd(&g_cursor[c], 1);
        g_src[g_off[c] + p] = row[e];
    }
}

// ---------------- tensor-core MLP ----------------
// y0 = dinv * (relu(x@W1+b1)@W2 + b2), fp16 inputs, fp32 accumulate.
// 128 rows / block, 8 warps; warp w owns rows [w*16, w*16+16), full 64 cols.
__global__ __launch_bounds__(256) void mlp_kernel(
    const float* __restrict__ x,
    const float* __restrict__ W1, const float* __restrict__ b1,
    const float* __restrict__ W2, const float* __restrict__ b2,
    const float* __restrict__ temp)
{
    __shared__ __half Ax[128][72];   // x tile (then h1 tile), padded pitch
    __shared__ __half Wt[64][72];    // W chunk transposed: Wt[n][k]

    const int t = threadIdx.x;
    const int lane = t & 31;
    const int w = t >> 5;
    const int row0 = blockIdx.x * 128;
    const int wr0 = w * 16;

    const int frow = lane >> 2;       // 0..7
    const int fkp  = (lane & 3) * 2;  // 0,2,4,6

    float c[8][4];
#pragma unroll
    for (int nt = 0; nt < 8; nt++)
#pragma unroll
        for (int i = 0; i < 4; i++) c[nt][i] = 0.0f;

    for (int s = 0; s < 8; s++) {
        const int k0 = s * 64;
        __syncthreads();
        // ---- stage x[rows, k0:k0+64] -> Ax (fp16), zero-pad beyond FD ----
        {
            int c4 = lane & 15;        // float4 index within 64 cols
            int hh = lane >> 4;        // 0/1
#pragma unroll
            for (int rr = 0; rr < 8; rr++) {
                int rl = rr * 2 + hh;
                int gr = row0 + wr0 + rl;
                int gk = k0 + c4 * 4;
                float4 xv = make_float4(0.f, 0.f, 0.f, 0.f);
                if (gr < NN && gk < FD)   // FD%4==0 so full float4 when gk<FD
                    xv = *reinterpret_cast<const float4*>(&x[(size_t)gr * FD + gk]);
                __half2 p0 = __floats2half2_rn(xv.x, xv.y);
                __half2 p1 = __floats2half2_rn(xv.z, xv.w);
                uint2 pk;
                pk.x = *reinterpret_cast<unsigned*>(&p0);
                pk.y = *reinterpret_cast<unsigned*>(&p1);
                *reinterpret_cast<uint2*>(&Ax[wr0 + rl][c4 * 4]) = pk;
            }
        }
        // ---- stage W1[k0:k0+64, :] transposed -> Wt[n][k] ----
        {
            int n = t & 63;
            int kb = t >> 6;           // 0..3
#pragma unroll
            for (int i = 0; i < 16; i++) {
                int kk = kb + i * 4;
                int gk = k0 + kk;
                Wt[n][kk] = (gk < FD) ? __float2half(W1[gk * 64 + n]) : __half(0.0f);
            }
        }
        __syncthreads();
        // ---- 4 mma k-steps ----
#pragma unroll
        for (int ks = 0; ks < 4; ks++) {
            const int kb = ks * 16;
            unsigned a0 = *reinterpret_cast<const unsigned*>(&Ax[wr0 + frow][kb + fkp]);
            unsigned a1 = *reinterpret_cast<const unsigned*>(&Ax[wr0 + frow + 8][kb + fkp]);
            unsigned a2 = *reinterpret_cast<const unsigned*>(&Ax[wr0 + frow][kb + fkp + 8]);
            unsigned a3 = *reinterpret_cast<const unsigned*>(&Ax[wr0 + frow + 8][kb + fkp + 8]);
#pragma unroll
            for (int nt = 0; nt < 8; nt++) {
                int n = nt * 8 + frow;
                unsigned b0 = *reinterpret_cast<const unsigned*>(&Wt[n][kb + fkp]);
                unsigned b1r = *reinterpret_cast<const unsigned*>(&Wt[n][kb + fkp + 8]);
                asm volatile(
                    "mma.sync.aligned.m16n8k16.row.col.f32.f16.f16.f32 "
                    "{%0,%1,%2,%3}, {%4,%5,%6,%7}, {%8,%9}, {%0,%1,%2,%3};"
                    : "+f"(c[nt][0]), "+f"(c[nt][1]), "+f"(c[nt][2]), "+f"(c[nt][3])
                    : "r"(a0), "r"(a1), "r"(a2), "r"(a3), "r"(b0), "r"(b1r));
            }
        }
    }

    // ---- epilogue 1: h1 = relu(c + b1) -> Ax (own rows only; no race) ----
#pragma unroll
    for (int nt = 0; nt < 8; nt++) {
        int n0 = nt * 8 + fkp;
        float2 bb = __ldg(reinterpret_cast<const float2*>(&b1[n0]));
        float h00 = fmaxf(c[nt][0] + bb.x, 0.f);
        float h01 = fmaxf(c[nt][1] + bb.y, 0.f);
        float h10 = fmaxf(c[nt][2] + bb.x, 0.f);
        float h11 = fmaxf(c[nt][3] + bb.y, 0.f);
        __half2 p0 = __floats2half2_rn(h00, h01);
        __half2 p1 = __floats2half2_rn(h10, h11);
        *reinterpret_cast<unsigned*>(&Ax[wr0 + frow][n0]) = *reinterpret_cast<unsigned*>(&p0);
        *reinterpret_cast<unsigned*>(&Ax[wr0 + frow + 8][n0]) = *reinterpret_cast<unsigned*>(&p1);
    }
    __syncthreads();   // all Wt reads done, all h1 writes done
    // ---- stage W2 transposed -> Wt ----
    {
        int n = t & 63;
        int kb = t >> 6;
#pragma unroll
        for (int i = 0; i < 16; i++) {
            int kk = kb + i * 4;
            Wt[n][kk] = __float2half(W2[kk * 64 + n]);
        }
    }
#pragma unroll
    for (int nt = 0; nt < 8; nt++)
#pragma unroll
        for (int i = 0; i < 4; i++) c[nt][i] = 0.0f;
    __syncthreads();

    // ---- GEMM2: h1 @ W2 (K = 64) ----
#pragma unroll
    for (int ks = 0; ks < 4; ks++) {
        const int kb = ks * 16;
        unsigned a0 = *reinterpret_cast<const unsigned*>(&Ax[wr0 + frow][kb + fkp]);
        unsigned a1 = *reinterpret_cast<const unsigned*>(&Ax[wr0 + frow + 8][kb + fkp]);
        unsigned a2 = *reinterpret_cast<const unsigned*>(&Ax[wr0 + frow][kb + fkp + 8]);
        unsigned a3 = *reinterpret_cast<const unsigned*>(&Ax[wr0 + frow + 8][kb + fkp + 8]);
#pragma unroll
        for (int nt = 0; nt < 8; nt++) {
            int n = nt * 8 + frow;
            unsigned b0 = *reinterpret_cast<const unsigned*>(&Wt[n][kb + fkp]);
            unsigned b1r = *reinterpret_cast<const unsigned*>(&Wt[n][kb + fkp + 8]);
            asm volatile(
                "mma.sync.aligned.m16n8k16.row.col.f32.f16.f16.f32 "
                "{%0,%1,%2,%3}, {%4,%5,%6,%7}, {%8,%9}, {%0,%1,%2,%3};"
                : "+f"(c[nt][0]), "+f"(c[nt][1]), "+f"(c[nt][2]), "+f"(c[nt][3])
                : "r"(a0), "r"(a1), "r"(a2), "r"(a3), "r"(b0), "r"(b1r));
        }
    }

    // ---- epilogue 2: y0 = dinv*(c+b2) -> g_yA (fp16), hidden = temp0*y0 (fp32) ----
    float t0 = __ldg(&temp[0]);
    int gr0 = row0 + wr0 + frow;
    int gr1 = gr0 + 8;
    float d0 = (gr0 < NN) ? g_dinv[gr0] : 0.f;
    float d1 = (gr1 < NN) ? g_dinv[gr1] : 0.f;
#pragma unroll
    for (int nt = 0; nt < 8; nt++) {
        int n0 = nt * 8 + fkp;
        float2 bb = __ldg(reinterpret_cast<const float2*>(&b2[n0]));
        float y00 = d0 * (c[nt][0] + bb.x);
        float y01 = d0 * (c[nt][1] + bb.y);
        float y10 = d1 * (c[nt][2] + bb.x);
        float y11 = d1 * (c[nt][3] + bb.y);
        if (gr0 < NN) {
            g_yA[(size_t)gr0 * 32 + n0 / 2] = __floats2half2_rn(y00, y01);
            *reinterpret_cast<float2*>(&g_hidden[(size_t)gr0 * NC + n0]) = make_float2(t0 * y00, t0 * y01);
        }
        if (gr1 < NN) {
            g_yA[(size_t)gr1 * 32 + n0 / 2] = __floats2half2_rn(y10, y11);
            *reinterpret_cast<float2*>(&g_hidden[(size_t)gr1 * NC + n0]) = make_float2(t0 * y10, t0 * y11);
        }
    }
}

// ---------------- pull propagation (R4 best): warp per node, fp16 gather, fp32 acc ----------------
__global__ __launch_bounds__(256) void propagate_kernel(const float* __restrict__ temp, int k, int flip) {
    const __half2* __restrict__ y = flip ? g_yB : g_yA;
    __half2* __restrict__ yn = flip ? g_yA : g_yB;
    int node = (blockIdx.x * blockDim.x + threadIdx.x) >> 5;
    int lane = threadIdx.x & 31;
    if (node >= NN) return;

    float d = g_dinv[node];
    size_t base2 = (size_t)node * 32 + lane;
    float2 self = __half22float2(y[base2]);
    float ax = self.x, ay = self.y;   // self-loop term: + y_k[c]

    int beg = g_off[node];
    int end = g_off[node + 1];
    int nfull = (end - beg) & ~31;
    int i = beg;
    for (; i < beg + nfull; i += 32) {
        int s = __ldg(&g_src[i + lane]);
#pragma unroll
        for (int j = 0; j < 32; j++) {
            int sj = __shfl_sync(0xFFFFFFFFu, s, j);
            float2 v = __half22float2(__ldg(&y[(size_t)sj * 32 + lane]));
            ax += v.x;
            ay += v.y;
        }
    }
    if (i < end) {
        int n = end - i;
        int s = (lane < n) ? __ldg(&g_src[i + lane]) : 0;
        for (int j = 0; j < n; j++) {
            int sj = __shfl_sync(0xFFFFFFFFu, s, j);
            float2 v = __half22float2(__ldg(&y[(size_t)sj * 32 + lane]));
            ax += v.x;
            ay += v.y;
        }
    }

    float d2 = d * d;
    float ox = d2 * ax, oy = d2 * ay;
    yn[base2] = __floats2half2_rn(ox, oy);

    float tk = temp[k + 1];
    float2 h = *reinterpret_cast<float2*>(&g_hidden[(size_t)node * NC + lane * 2]);
    h.x += tk * ox;
    h.y += tk * oy;
    *reinterpret_cast<float2*>(&g_hidden[(size_t)node * NC + lane * 2]) = h;
}

// ---------------- final: out = log_softmax(hs * sqrt(deg)) ----------------
__global__ void final_kernel(float* __restrict__ out) {
    int warp = (blockIdx.x * blockDim.x + threadIdx.x) >> 5;
    int lane = threadIdx.x & 31;
    if (warp >= NN) return;
    float sd = g_sdeg[warp];
    size_t base = (size_t)warp * NC;
    float a = g_hidden[base + lane] * sd;
    float b = g_hidden[base + 32 + lane] * sd;
    float mx = fmaxf(a, b);
#pragma unroll
    for (int off = 16; off > 0; off >>= 1)
        mx = fmaxf(mx, __shfl_xor_sync(0xFFFFFFFFu, mx, off));
    float s = expf(a - mx) + expf(b - mx);
#pragma unroll
    for (int off = 16; off > 0; off >>= 1)
        s += __shfl_xor_sync(0xFFFFFFFFu, s, off);
    float l = mx + logf(s);
    out[base + lane] = a - l;
    out[base + 32 + lane] = b - l;
}

// ---------------- launch ----------------
extern "C" void kernel_launch(void* const* d_in, const int* in_sizes, int n_in,
                              void* d_out, int out_size)
{
    const float* x    = (const float*)d_in[0];
    const int*   ei   = (const int*)d_in[1];
    const float* W1   = (const float*)d_in[2];
    const float* b1   = (const float*)d_in[3];
    const float* W2   = (const float*)d_in[4];
    const float* b2   = (const float*)d_in[5];
    const float* temp = (const float*)d_in[6];
    float* out = (float*)d_out;

    const int E = in_sizes[1] / 2;
    const int* row = ei;       // source
    const int* col = ei + E;   // target

    // launches 0..2, then MLP at index 3 (ncu capture slot)
    cnt_zero_kernel<<<(NN + 255) / 256, 256>>>();
    cnt_acc_kernel<<<(E + 255) / 256, 256>>>(col, E);
    dinv_kernel<<<(NN + 255) / 256, 256>>>();
    mlp_kernel<<<(NN + 127) / 128, 256>>>(x, W1, b1, W2, b2, temp);

    // CSR build
    scan1_kernel<<<NB_SCAN, 1024>>>();
    scan2_kernel<<<1, 32>>>();
    scan3_kernel<<<NB_SCAN, 1024>>>();
    fill_kernel<<<(E + 255) / 256, 256>>>(row, col, E);

    // pull propagation: 1 warp per node
    int pblocks = (NN * 32 + 255) / 256;
    for (int k = 0; k < KH; k++) {
        propagate_kernel<<<pblocks, 256>>>(temp, k, k & 1);
    }

    final_kernel<<<(NN * 32 + 255) / 256, 256>>>(out);
}

// round 8
// speedup vs baseline: 1.5179x; 1.0982x over previous
#include <cuda_runtime.h>
#include <cuda_fp16.h>
#include <math.h>

#define NN 100000
#define FD 500
#define NC 64
#define KH 10
#define EMAX 3200000
#define NB_SCAN ((NN + 1023) / 1024)
#define SLICE ((size_t)(NN + 1) * 32)   // half2 per y slice (+1 sentinel row)

// ---- scratch (no allocations allowed) ----
__device__ __half2 g_yH[(size_t)(KH + 1) * SLICE]; // y_0..y_K history (fp16)
__device__ float g_dinv[NN];
__device__ float g_sdeg[NN];
__device__ int   g_cnt[NN];
__device__ int   g_cursor[NN];
__device__ int   g_off[NN + 1];
__device__ int   g_bsum[NB_SCAN];
__device__ int   g_src[EMAX];

// ---------------- in-degree count ----------------
__global__ void cnt_zero_kernel() {
    int i = blockIdx.x * blockDim.x + threadIdx.x;
    if (i < NN) g_cnt[i] = 0;
}

__global__ void cnt_acc_kernel(const int* __restrict__ col, int E) {
    int e = blockIdx.x * blockDim.x + threadIdx.x;
    if (e < E) atomicAdd(&g_cnt[col[e]], 1);
}

// dinv/sdeg from counts (runs before mlp so mlp sits at ncu capture slot 3)
__global__ void dinv_kernel() {
    int i = blockIdx.x * blockDim.x + threadIdx.x;
    if (i < NN) {
        float deg = (float)(g_cnt[i] + 1);   // + self loop
        g_dinv[i] = rsqrtf(deg);
        g_sdeg[i] = sqrtf(deg);
        g_cursor[i] = 0;
    }
}

// ---------------- scan ----------------
__global__ __launch_bounds__(1024) void scan1_kernel() {
    __shared__ int sh[1024];
    int i = blockIdx.x * 1024 + threadIdx.x;
    int v = (i < NN) ? g_cnt[i] : 0;
    sh[threadIdx.x] = v;
    __syncthreads();
#pragma unroll
    for (int off = 1; off < 1024; off <<= 1) {
        int t = 0;
        if (threadIdx.x >= off) t = sh[threadIdx.x - off];
        __syncthreads();
        if (threadIdx.x >= off) sh[threadIdx.x] += t;
        __syncthreads();
    }
    if (i < NN) g_off[i] = sh[threadIdx.x] - v;
    if (threadIdx.x == 1023) g_bsum[blockIdx.x] = sh[1023];
}

// warp-scan over the ~98 block sums
__global__ void scan2_kernel() {
    int lane = threadIdx.x;
    int run = 0;
    for (int b0 = 0; b0 < NB_SCAN; b0 += 32) {
        int idx = b0 + lane;
        int orig = (idx < NB_SCAN) ? g_bsum[idx] : 0;
        int v = orig;
#pragma unroll
        for (int off = 1; off < 32; off <<= 1) {
            int t = __shfl_up_sync(0xFFFFFFFFu, v, off);
            if (lane >= off) v += t;
        }
        if (idx < NB_SCAN) g_bsum[idx] = run + v - orig;  // exclusive
        run += __shfl_sync(0xFFFFFFFFu, v, 31);
    }
    if (lane == 0) g_off[NN] = run;
}

__global__ __launch_bounds__(1024) void scan3_kernel() {
    int i = blockIdx.x * 1024 + threadIdx.x;
    if (i < NN) g_off[i] += g_bsum[blockIdx.x];
}

// ---------------- CSR fill ----------------
__global__ void fill_kernel(const int* __restrict__ row, const int* __restrict__ col, int E) {
    int e = blockIdx.x * blockDim.x + threadIdx.x;
    if (e < E) {
        int c = col[e];
        int p = atomicAdd(&g_cursor[c], 1);
        g_src[g_off[c] + p] = row[e];
    }
}

// zero the sentinel row (index NN) in every history slice
__global__ void sentinel_kernel() {
    int i = blockIdx.x * blockDim.x + threadIdx.x;
    if (i < (KH + 1) * 32) {
        int k = i >> 5, l = i & 31;
        g_yH[(size_t)k * SLICE + (size_t)NN * 32 + l] = __float2half2_rn(0.0f);
    }
}

// ---------------- tensor-core MLP ----------------
// y0 = dinv * (relu(x@W1+b1)@W2 + b2) -> g_yH slice 0 (fp16)
__global__ __launch_bounds__(256) void mlp_kernel(
    const float* __restrict__ x,
    const float* __restrict__ W1, const float* __restrict__ b1,
    const float* __restrict__ W2, const float* __restrict__ b2)
{
    __shared__ __half Ax[128][72];   // x tile (then h1 tile), padded pitch
    __shared__ __half Wt[64][72];    // W chunk transposed: Wt[n][k]

    const int t = threadIdx.x;
    const int lane = t & 31;
    const int w = t >> 5;
    const int row0 = blockIdx.x * 128;
    const int wr0 = w * 16;

    const int frow = lane >> 2;       // 0..7
    const int fkp  = (lane & 3) * 2;  // 0,2,4,6

    float c[8][4];
#pragma unroll
    for (int nt = 0; nt < 8; nt++)
#pragma unroll
        for (int i = 0; i < 4; i++) c[nt][i] = 0.0f;

    for (int s = 0; s < 8; s++) {
        const int k0 = s * 64;
        __syncthreads();
        // ---- stage x[rows, k0:k0+64] -> Ax (fp16), zero-pad beyond FD ----
        {
            int c4 = lane & 15;
            int hh = lane >> 4;
#pragma unroll
            for (int rr = 0; rr < 8; rr++) {
                int rl = rr * 2 + hh;
                int gr = row0 + wr0 + rl;
                int gk = k0 + c4 * 4;
                float4 xv = make_float4(0.f, 0.f, 0.f, 0.f);
                if (gr < NN && gk < FD)
                    xv = *reinterpret_cast<const float4*>(&x[(size_t)gr * FD + gk]);
                __half2 p0 = __floats2half2_rn(xv.x, xv.y);
                __half2 p1 = __floats2half2_rn(xv.z, xv.w);
                uint2 pk;
                pk.x = *reinterpret_cast<unsigned*>(&p0);
                pk.y = *reinterpret_cast<unsigned*>(&p1);
                *reinterpret_cast<uint2*>(&Ax[wr0 + rl][c4 * 4]) = pk;
            }
        }
        // ---- stage W1[k0:k0+64, :] transposed -> Wt[n][k] ----
        {
            int n = t & 63;
            int kb = t >> 6;
#pragma unroll
            for (int i = 0; i < 16; i++) {
                int kk = kb + i * 4;
                int gk = k0 + kk;
                Wt[n][kk] = (gk < FD) ? __float2half(W1[gk * 64 + n]) : __half(0.0f);
            }
        }
        __syncthreads();
#pragma unroll
        for (int ks = 0; ks < 4; ks++) {
            const int kb = ks * 16;
            unsigned a0 = *reinterpret_cast<const unsigned*>(&Ax[wr0 + frow][kb + fkp]);
            unsigned a1 = *reinterpret_cast<const unsigned*>(&Ax[wr0 + frow + 8][kb + fkp]);
            unsigned a2 = *reinterpret_cast<const unsigned*>(&Ax[wr0 + frow][kb + fkp + 8]);
            unsigned a3 = *reinterpret_cast<const unsigned*>(&Ax[wr0 + frow + 8][kb + fkp + 8]);
#pragma unroll
            for (int nt = 0; nt < 8; nt++) {
                int n = nt * 8 + frow;
                unsigned b0 = *reinterpret_cast<const unsigned*>(&Wt[n][kb + fkp]);
                unsigned b1r = *reinterpret_cast<const unsigned*>(&Wt[n][kb + fkp + 8]);
                asm volatile(
                    "mma.sync.aligned.m16n8k16.row.col.f32.f16.f16.f32 "
                    "{%0,%1,%2,%3}, {%4,%5,%6,%7}, {%8,%9}, {%0,%1,%2,%3};"
                    : "+f"(c[nt][0]), "+f"(c[nt][1]), "+f"(c[nt][2]), "+f"(c[nt][3])
                    : "r"(a0), "r"(a1), "r"(a2), "r"(a3), "r"(b0), "r"(b1r));
            }
        }
    }

    // ---- epilogue 1: h1 = relu(c + b1) -> Ax ----
#pragma unroll
    for (int nt = 0; nt < 8; nt++) {
        int n0 = nt * 8 + fkp;
        float2 bb = __ldg(reinterpret_cast<const float2*>(&b1[n0]));
        float h00 = fmaxf(c[nt][0] + bb.x, 0.f);
        float h01 = fmaxf(c[nt][1] + bb.y, 0.f);
        float h10 = fmaxf(c[nt][2] + bb.x, 0.f);
        float h11 = fmaxf(c[nt][3] + bb.y, 0.f);
        __half2 p0 = __floats2half2_rn(h00, h01);
        __half2 p1 = __floats2half2_rn(h10, h11);
        *reinterpret_cast<unsigned*>(&Ax[wr0 + frow][n0]) = *reinterpret_cast<unsigned*>(&p0);
        *reinterpret_cast<unsigned*>(&Ax[wr0 + frow + 8][n0]) = *reinterpret_cast<unsigned*>(&p1);
    }
    __syncthreads();
    // ---- stage W2 transposed -> Wt ----
    {
        int n = t & 63;
        int kb = t >> 6;
#pragma unroll
        for (int i = 0; i < 16; i++) {
            int kk = kb + i * 4;
            Wt[n][kk] = __float2half(W2[kk * 64 + n]);
        }
    }
#pragma unroll
    for (int nt = 0; nt < 8; nt++)
#pragma unroll
        for (int i = 0; i < 4; i++) c[nt][i] = 0.0f;
    __syncthreads();

    // ---- GEMM2: h1 @ W2 ----
#pragma unroll
    for (int ks = 0; ks < 4; ks++) {
        const int kb = ks * 16;
        unsigned a0 = *reinterpret_cast<const unsigned*>(&Ax[wr0 + frow][kb + fkp]);
        unsigned a1 = *reinterpret_cast<const unsigned*>(&Ax[wr0 + frow + 8][kb + fkp]);
        unsigned a2 = *reinterpret_cast<const unsigned*>(&Ax[wr0 + frow][kb + fkp + 8]);
        unsigned a3 = *reinterpret_cast<const unsigned*>(&Ax[wr0 + frow + 8][kb + fkp + 8]);
#pragma unroll
        for (int nt = 0; nt < 8; nt++) {
            int n = nt * 8 + frow;
            unsigned b0 = *reinterpret_cast<const unsigned*>(&Wt[n][kb + fkp]);
            unsigned b1r = *reinterpret_cast<const unsigned*>(&Wt[n][kb + fkp + 8]);
            asm volatile(
                "mma.sync.aligned.m16n8k16.row.col.f32.f16.f16.f32 "
                "{%0,%1,%2,%3}, {%4,%5,%6,%7}, {%8,%9}, {%0,%1,%2,%3};"
                : "+f"(c[nt][0]), "+f"(c[nt][1]), "+f"(c[nt][2]), "+f"(c[nt][3])
                : "r"(a0), "r"(a1), "r"(a2), "r"(a3), "r"(b0), "r"(b1r));
        }
    }

    // ---- epilogue 2: y0 = dinv*(c+b2) -> g_yH slice 0 ----
    int gr0 = row0 + wr0 + frow;
    int gr1 = gr0 + 8;
    float d0 = (gr0 < NN) ? g_dinv[gr0] : 0.f;
    float d1 = (gr1 < NN) ? g_dinv[gr1] : 0.f;
#pragma unroll
    for (int nt = 0; nt < 8; nt++) {
        int n0 = nt * 8 + fkp;
        float2 bb = __ldg(reinterpret_cast<const float2*>(&b2[n0]));
        float y00 = d0 * (c[nt][0] + bb.x);
        float y01 = d0 * (c[nt][1] + bb.y);
        float y10 = d1 * (c[nt][2] + bb.x);
        float y11 = d1 * (c[nt][3] + bb.y);
        if (gr0 < NN) g_yH[(size_t)gr0 * 32 + n0 / 2] = __floats2half2_rn(y00, y01);
        if (gr1 < NN) g_yH[(size_t)gr1 * 32 + n0 / 2] = __floats2half2_rn(y10, y11);
    }
}

// ---------------- pull propagation: warp per node, HADD2 chunks of 8 ----------------
// y_{k+1}[c] = d^2 * ( sum_{r in N_in(c)} y_k[r] + y_k[c] )
__global__ __launch_bounds__(256) void propagate_kernel(int k) {
    const __half2* __restrict__ y = g_yH + (size_t)k * SLICE;
    __half2* __restrict__ yn = g_yH + (size_t)(k + 1) * SLICE;
    int node = (blockIdx.x * blockDim.x + threadIdx.x) >> 5;
    int lane = threadIdx.x & 31;
    if (node >= NN) return;

    float d = g_dinv[node];
    float2 self = __half22float2(y[(size_t)node * 32 + lane]);
    float ax = self.x, ay = self.y;   // self-loop term

    int beg = g_off[node];
    int end = g_off[node + 1];
    for (int i = beg; i < end; i += 32) {
        int s = (i + lane < end) ? __ldg(&g_src[i + lane]) : NN;  // sentinel zero row
#pragma unroll
        for (int t = 0; t < 4; t++) {
            if (i + t * 8 < end) {
                __half2 hacc = __float2half2_rn(0.0f);
#pragma unroll
                for (int j = 0; j < 8; j++) {
                    int sj = __shfl_sync(0xFFFFFFFFu, s, t * 8 + j);
                    hacc = __hadd2(hacc, __ldg(&y[(size_t)sj * 32 + lane]));
                }
                float2 f = __half22float2(hacc);
                ax += f.x;
                ay += f.y;
            }
        }
    }

    float d2 = d * d;
    yn[(size_t)node * 32 + lane] = __floats2half2_rn(d2 * ax, d2 * ay);
}

// ---------------- final: hidden = sdeg * sum_k temp[k]*y_k ; log_softmax ----------------
__global__ void final_kernel(const float* __restrict__ temp, float* __restrict__ out) {
    int node = (blockIdx.x * blockDim.x + threadIdx.x) >> 5;
    int lane = threadIdx.x & 31;
    if (node >= NN) return;
    float sd = g_sdeg[node];
    float ax = 0.f, ay = 0.f;
#pragma unroll
    for (int k = 0; k <= KH; k++) {
        float tk = __ldg(&temp[k]);
        float2 v = __half22float2(__ldg(&g_yH[(size_t)k * SLICE + (size_t)node * 32 + lane]));
        ax += tk * v.x;
        ay += tk * v.y;
    }
    float a = ax * sd, b = ay * sd;   // features 2*lane, 2*lane+1
    float mx = fmaxf(a, b);
#pragma unroll
    for (int off = 16; off > 0; off >>= 1)
        mx = fmaxf(mx, __shfl_xor_sync(0xFFFFFFFFu, mx, off));
    float s = expf(a - mx) + expf(b - mx);
#pragma unroll
    for (int off = 16; off > 0; off >>= 1)
        s += __shfl_xor_sync(0xFFFFFFFFu, s, off);
    float l = mx + logf(s);
    *reinterpret_cast<float2*>(&out[(size_t)node * NC + lane * 2]) = make_float2(a - l, b - l);
}

// ---------------- launch ----------------
extern "C" void kernel_launch(void* const* d_in, const int* in_sizes, int n_in,
                              void* d_out, int out_size)
{
    const float* x    = (const float*)d_in[0];
    const int*   ei   = (const int*)d_in[1];
    const float* W1   = (const float*)d_in[2];
    const float* b1   = (const float*)d_in[3];
    const float* W2   = (const float*)d_in[4];
    const float* b2   = (const float*)d_in[5];
    const float* temp = (const float*)d_in[6];
    float* out = (float*)d_out;

    const int E = in_sizes[1] / 2;
    const int* row = ei;       // source
    const int* col = ei + E;   // target

    // launches 0..2, then MLP at index 3 (ncu capture slot)
    cnt_zero_kernel<<<(NN + 255) / 256, 256>>>();
    cnt_acc_kernel<<<(E + 255) / 256, 256>>>(col, E);
    dinv_kernel<<<(NN + 255) / 256, 256>>>();
    mlp_kernel<<<(NN + 127) / 128, 256>>>(x, W1, b1, W2, b2);

    // CSR build
    scan1_kernel<<<NB_SCAN, 1024>>>();
    scan2_kernel<<<1, 32>>>();
    scan3_kernel<<<NB_SCAN, 1024>>>();
    fill_kernel<<<(E + 255) / 256, 256>>>(row, col, E);
    sentinel_kernel<<<2, 256>>>();

    // pull propagation: 1 warp per node, y_k history in g_yH
    int pblocks = (NN * 32 + 255) / 256;
    for (int k = 0; k < KH; k++) {
        propagate_kernel<<<pblocks, 256>>>(k);
    }

    final_kernel<<<(NN * 32 + 255) / 256, 256>>>(temp, out);
}

// round 9
// speedup vs baseline: 1.6031x; 1.0562x over previous
#include <cuda_runtime.h>
#include <cuda_fp16.h>
#include <math.h>

#define NN 100000
#define FD 500
#define NC 64
#define KH 10
#define EMAX 3200000
#define NB_SCAN ((NN + 1023) / 1024)
#define SLICE ((size_t)(NN + 1) * 32)   // half2 per y slice (+1 sentinel row)

// ---- scratch (no allocations allowed) ----
__device__ __half2 g_yH[(size_t)(KH + 1) * SLICE]; // y_0..y_K history (fp16)
__device__ float g_dinv[NN];
__device__ float g_sdeg[NN];
__device__ int   g_cnt[NN];
__device__ int   g_cursor[NN];
__device__ int   g_off[NN + 1];
__device__ int   g_bsum[NB_SCAN];
__device__ int   g_src[EMAX];

// ---------------- in-degree count ----------------
__global__ void cnt_zero_kernel() {
    int i = blockIdx.x * blockDim.x + threadIdx.x;
    if (i < NN) g_cnt[i] = 0;
}

__global__ void cnt_acc_kernel(const int* __restrict__ col, int E) {
    int e = blockIdx.x * blockDim.x + threadIdx.x;
    if (e < E) atomicAdd(&g_cnt[col[e]], 1);
}

// dinv/sdeg from counts (runs before mlp so mlp sits at ncu capture slot 3)
__global__ void dinv_kernel() {
    int i = blockIdx.x * blockDim.x + threadIdx.x;
    if (i < NN) {
        float deg = (float)(g_cnt[i] + 1);   // + self loop
        g_dinv[i] = rsqrtf(deg);
        g_sdeg[i] = sqrtf(deg);
        g_cursor[i] = 0;
    }
}

// ---------------- scan ----------------
__global__ __launch_bounds__(1024) void scan1_kernel() {
    __shared__ int sh[1024];
    int i = blockIdx.x * 1024 + threadIdx.x;
    int v = (i < NN) ? g_cnt[i] : 0;
    sh[threadIdx.x] = v;
    __syncthreads();
#pragma unroll
    for (int off = 1; off < 1024; off <<= 1) {
        int t = 0;
        if (threadIdx.x >= off) t = sh[threadIdx.x - off];
        __syncthreads();
        if (threadIdx.x >= off) sh[threadIdx.x] += t;
        __syncthreads();
    }
    if (i < NN) g_off[i] = sh[threadIdx.x] - v;
    if (threadIdx.x == 1023) g_bsum[blockIdx.x] = sh[1023];
}

// warp-scan over the ~98 block sums
__global__ void scan2_kernel() {
    int lane = threadIdx.x;
    int run = 0;
    for (int b0 = 0; b0 < NB_SCAN; b0 += 32) {
        int idx = b0 + lane;
        int orig = (idx < NB_SCAN) ? g_bsum[idx] : 0;
        int v = orig;
#pragma unroll
        for (int off = 1; off < 32; off <<= 1) {
            int t = __shfl_up_sync(0xFFFFFFFFu, v, off);
            if (lane >= off) v += t;
        }
        if (idx < NB_SCAN) g_bsum[idx] = run + v - orig;  // exclusive
        run += __shfl_sync(0xFFFFFFFFu, v, 31);
    }
    if (lane == 0) g_off[NN] = run;
}

__global__ __launch_bounds__(1024) void scan3_kernel() {
    int i = blockIdx.x * 1024 + threadIdx.x;
    if (i < NN) g_off[i] += g_bsum[blockIdx.x];
}

// ---------------- CSR fill ----------------
__global__ void fill_kernel(const int* __restrict__ row, const int* __restrict__ col, int E) {
    int e = blockIdx.x * blockDim.x + threadIdx.x;
    if (e < E) {
        int c = col[e];
        int p = atomicAdd(&g_cursor[c], 1);
        g_src[g_off[c] + p] = row[e];
    }
}

// zero the sentinel row (index NN) in every history slice
__global__ void sentinel_kernel() {
    int i = blockIdx.x * blockDim.x + threadIdx.x;
    if (i < (KH + 1) * 32) {
        int k = i >> 5, l = i & 31;
        g_yH[(size_t)k * SLICE + (size_t)NN * 32 + l] = __float2half2_rn(0.0f);
    }
}

// ---------------- tensor-core MLP ----------------
// y0 = dinv * (relu(x@W1+b1)@W2 + b2) -> g_yH slice 0 (fp16)
__global__ __launch_bounds__(256) void mlp_kernel(
    const float* __restrict__ x,
    const float* __restrict__ W1, const float* __restrict__ b1,
    const float* __restrict__ W2, const float* __restrict__ b2)
{
    __shared__ __half Ax[128][72];   // x tile (then h1 tile), padded pitch
    __shared__ __half Wt[64][72];    // W chunk transposed: Wt[n][k]

    const int t = threadIdx.x;
    const int lane = t & 31;
    const int w = t >> 5;
    const int row0 = blockIdx.x * 128;
    const int wr0 = w * 16;

    const int frow = lane >> 2;       // 0..7
    const int fkp  = (lane & 3) * 2;  // 0,2,4,6

    float c[8][4];
#pragma unroll
    for (int nt = 0; nt < 8; nt++)
#pragma unroll
        for (int i = 0; i < 4; i++) c[nt][i] = 0.0f;

    for (int s = 0; s < 8; s++) {
        const int k0 = s * 64;
        __syncthreads();
        // ---- stage x[rows, k0:k0+64] -> Ax (fp16), zero-pad beyond FD ----
        {
            int c4 = lane & 15;
            int hh = lane >> 4;
#pragma unroll
            for (int rr = 0; rr < 8; rr++) {
                int rl = rr * 2 + hh;
                int gr = row0 + wr0 + rl;
                int gk = k0 + c4 * 4;
                float4 xv = make_float4(0.f, 0.f, 0.f, 0.f);
                if (gr < NN && gk < FD)
                    xv = *reinterpret_cast<const float4*>(&x[(size_t)gr * FD + gk]);
                __half2 p0 = __floats2half2_rn(xv.x, xv.y);
                __half2 p1 = __floats2half2_rn(xv.z, xv.w);
                uint2 pk;
                pk.x = *reinterpret_cast<unsigned*>(&p0);
                pk.y = *reinterpret_cast<unsigned*>(&p1);
                *reinterpret_cast<uint2*>(&Ax[wr0 + rl][c4 * 4]) = pk;
            }
        }
        // ---- stage W1[k0:k0+64, :] transposed -> Wt[n][k] ----
        {
            int n = t & 63;
            int kb = t >> 6;
#pragma unroll
            for (int i = 0; i < 16; i++) {
                int kk = kb + i * 4;
                int gk = k0 + kk;
                Wt[n][kk] = (gk < FD) ? __float2half(W1[gk * 64 + n]) : __half(0.0f);
            }
        }
        __syncthreads();
#pragma unroll
        for (int ks = 0; ks < 4; ks++) {
            const int kb = ks * 16;
            unsigned a0 = *reinterpret_cast<const unsigned*>(&Ax[wr0 + frow][kb + fkp]);
            unsigned a1 = *reinterpret_cast<const unsigned*>(&Ax[wr0 + frow + 8][kb + fkp]);
            unsigned a2 = *reinterpret_cast<const unsigned*>(&Ax[wr0 + frow][kb + fkp + 8]);
            unsigned a3 = *reinterpret_cast<const unsigned*>(&Ax[wr0 + frow + 8][kb + fkp + 8]);
#pragma unroll
            for (int nt = 0; nt < 8; nt++) {
                int n = nt * 8 + frow;
                unsigned b0 = *reinterpret_cast<const unsigned*>(&Wt[n][kb + fkp]);
                unsigned b1r = *reinterpret_cast<const unsigned*>(&Wt[n][kb + fkp + 8]);
                asm volatile(
                    "mma.sync.aligned.m16n8k16.row.col.f32.f16.f16.f32 "
                    "{%0,%1,%2,%3}, {%4,%5,%6,%7}, {%8,%9}, {%0,%1,%2,%3};"
                    : "+f"(c[nt][0]), "+f"(c[nt][1]), "+f"(c[nt][2]), "+f"(c[nt][3])
                    : "r"(a0), "r"(a1), "r"(a2), "r"(a3), "r"(b0), "r"(b1r));
            }
        }
    }

    // ---- epilogue 1: h1 = relu(c + b1) -> Ax ----
#pragma unroll
    for (int nt = 0; nt < 8; nt++) {
        int n0 = nt * 8 + fkp;
        float2 bb = __ldg(reinterpret_cast<const float2*>(&b1[n0]));
        float h00 = fmaxf(c[nt][0] + bb.x, 0.f);
        float h01 = fmaxf(c[nt][1] + bb.y, 0.f);
        float h10 = fmaxf(c[nt][2] + bb.x, 0.f);
        float h11 = fmaxf(c[nt][3] + bb.y, 0.f);
        __half2 p0 = __floats2half2_rn(h00, h01);
        __half2 p1 = __floats2half2_rn(h10, h11);
        *reinterpret_cast<unsigned*>(&Ax[wr0 + frow][n0]) = *reinterpret_cast<unsigned*>(&p0);
        *reinterpret_cast<unsigned*>(&Ax[wr0 + frow + 8][n0]) = *reinterpret_cast<unsigned*>(&p1);
    }
    __syncthreads();
    // ---- stage W2 transposed -> Wt ----
    {
        int n = t & 63;
        int kb = t >> 6;
#pragma unroll
        for (int i = 0; i < 16; i++) {
            int kk = kb + i * 4;
            Wt[n][kk] = __float2half(W2[kk * 64 + n]);
        }
    }
#pragma unroll
    for (int nt = 0; nt < 8; nt++)
#pragma unroll
        for (int i = 0; i < 4; i++) c[nt][i] = 0.0f;
    __syncthreads();

    // ---- GEMM2: h1 @ W2 ----
#pragma unroll
    for (int ks = 0; ks < 4; ks++) {
        const int kb = ks * 16;
        unsigned a0 = *reinterpret_cast<const unsigned*>(&Ax[wr0 + frow][kb + fkp]);
        unsigned a1 = *reinterpret_cast<const unsigned*>(&Ax[wr0 + frow + 8][kb + fkp]);
        unsigned a2 = *reinterpret_cast<const unsigned*>(&Ax[wr0 + frow][kb + fkp + 8]);
        unsigned a3 = *reinterpret_cast<const unsigned*>(&Ax[wr0 + frow + 8][kb + fkp + 8]);
#pragma unroll
        for (int nt = 0; nt < 8; nt++) {
            int n = nt * 8 + frow;
            unsigned b0 = *reinterpret_cast<const unsigned*>(&Wt[n][kb + fkp]);
            unsigned b1r = *reinterpret_cast<const unsigned*>(&Wt[n][kb + fkp + 8]);
            asm volatile(
                "mma.sync.aligned.m16n8k16.row.col.f32.f16.f16.f32 "
                "{%0,%1,%2,%3}, {%4,%5,%6,%7}, {%8,%9}, {%0,%1,%2,%3};"
                : "+f"(c[nt][0]), "+f"(c[nt][1]), "+f"(c[nt][2]), "+f"(c[nt][3])
                : "r"(a0), "r"(a1), "r"(a2), "r"(a3), "r"(b0), "r"(b1r));
        }
    }

    // ---- epilogue 2: y0 = dinv*(c+b2) -> g_yH slice 0 ----
    int gr0 = row0 + wr0 + frow;
    int gr1 = gr0 + 8;
    float d0 = (gr0 < NN) ? g_dinv[gr0] : 0.f;
    float d1 = (gr1 < NN) ? g_dinv[gr1] : 0.f;
#pragma unroll
    for (int nt = 0; nt < 8; nt++) {
        int n0 = nt * 8 + fkp;
        float2 bb = __ldg(reinterpret_cast<const float2*>(&b2[n0]));
        float y00 = d0 * (c[nt][0] + bb.x);
        float y01 = d0 * (c[nt][1] + bb.y);
        float y10 = d1 * (c[nt][2] + bb.x);
        float y11 = d1 * (c[nt][3] + bb.y);
        if (gr0 < NN) g_yH[(size_t)gr0 * 32 + n0 / 2] = __floats2half2_rn(y00, y01);
        if (gr1 < NN) g_yH[(size_t)gr1 * 32 + n0 / 2] = __floats2half2_rn(y10, y11);
    }
}

// ---------------- pull propagation: warp per node ----------------
// full 32-edge blocks: guard-free, 4 chunks x (2 HADD2 chains of 4); tail guarded per 8.
__global__ __launch_bounds__(256) void propagate_kernel(int k) {
    const __half2* __restrict__ y = g_yH + (size_t)k * SLICE;
    __half2* __restrict__ yn = g_yH + (size_t)(k + 1) * SLICE;
    int node = (blockIdx.x * blockDim.x + threadIdx.x) >> 5;
    int lane = threadIdx.x & 31;
    if (node >= NN) return;

    float d = g_dinv[node];
    float2 self = __half22float2(__ldg(&y[(size_t)node * 32 + lane]));
    float ax = self.x, ay = self.y;   // self-loop term

    int beg = g_off[node];
    int end = g_off[node + 1];
    int nfull = (end - beg) & ~31;
    int i = beg;

    // ---- full 32-edge blocks: no guards inside ----
    for (; i < beg + nfull; i += 32) {
        int s = __ldg(&g_src[i + lane]);
#pragma unroll
        for (int t = 0; t < 4; t++) {
            __half2 h0 = __float2half2_rn(0.0f);
            __half2 h1 = __float2half2_rn(0.0f);
#pragma unroll
            for (int j = 0; j < 4; j++) {
                int sj0 = __shfl_sync(0xFFFFFFFFu, s, t * 8 + j);
                int sj1 = __shfl_sync(0xFFFFFFFFu, s, t * 8 + 4 + j);
                h0 = __hadd2(h0, __ldg(&y[(size_t)sj0 * 32 + lane]));
                h1 = __hadd2(h1, __ldg(&y[(size_t)sj1 * 32 + lane]));
            }
            float2 f = __half22float2(__hadd2(h0, h1));
            ax += f.x;
            ay += f.y;
        }
    }

    // ---- tail (< 32 edges): guarded per 8-chunk ----
    if (i < end) {
        int s = (i + lane < end) ? __ldg(&g_src[i + lane]) : NN;  // sentinel zero row
#pragma unroll
        for (int t = 0; t < 4; t++) {
            if (i + t * 8 < end) {
                __half2 h0 = __float2half2_rn(0.0f);
                __half2 h1 = __float2half2_rn(0.0f);
#pragma unroll
                for (int j = 0; j < 4; j++) {
                    int sj0 = __shfl_sync(0xFFFFFFFFu, s, t * 8 + j);
                    int sj1 = __shfl_sync(0xFFFFFFFFu, s, t * 8 + 4 + j);
                    h0 = __hadd2(h0, __ldg(&y[(size_t)sj0 * 32 + lane]));
                    h1 = __hadd2(h1, __ldg(&y[(size_t)sj1 * 32 + lane]));
                }
                float2 f = __half22float2(__hadd2(h0, h1));
                ax += f.x;
                ay += f.y;
            }
        }
    }

    float d2 = d * d;
    yn[(size_t)node * 32 + lane] = __floats2half2_rn(d2 * ax, d2 * ay);
}

// ---------------- final: hidden = sdeg * sum_k temp[k]*y_k ; log_softmax ----------------
__global__ void final_kernel(const float* __restrict__ temp, float* __restrict__ out) {
    int node = (blockIdx.x * blockDim.x + threadIdx.x) >> 5;
    int lane = threadIdx.x & 31;
    if (node >= NN) return;
    float sd = g_sdeg[node];
    float ax = 0.f, ay = 0.f;
#pragma unroll
    for (int k = 0; k <= KH; k++) {
        float tk = __ldg(&temp[k]);
        float2 v = __half22float2(__ldg(&g_yH[(size_t)k * SLICE + (size_t)node * 32 + lane]));
        ax += tk * v.x;
        ay += tk * v.y;
    }
    float a = ax * sd, b = ay * sd;   // features 2*lane, 2*lane+1
    float mx = fmaxf(a, b);
#pragma unroll
    for (int off = 16; off > 0; off >>= 1)
        mx = fmaxf(mx, __shfl_xor_sync(0xFFFFFFFFu, mx, off));
    float s = expf(a - mx) + expf(b - mx);
#pragma unroll
    for (int off = 16; off > 0; off >>= 1)
        s += __shfl_xor_sync(0xFFFFFFFFu, s, off);
    float l = mx + logf(s);
    *reinterpret_cast<float2*>(&out[(size_t)node * NC + lane * 2]) = make_float2(a - l, b - l);
}

// ---------------- launch ----------------
extern "C" void kernel_launch(void* const* d_in, const int* in_sizes, int n_in,
                              void* d_out, int out_size)
{
    const float* x    = (const float*)d_in[0];
    const int*   ei   = (const int*)d_in[1];
    const float* W1   = (const float*)d_in[2];
    const float* b1   = (const float*)d_in[3];
    const float* W2   = (const float*)d_in[4];
    const float* b2   = (const float*)d_in[5];
    const float* temp = (const float*)d_in[6];
    float* out = (float*)d_out;

    const int E = in_sizes[1] / 2;
    const int* row = ei;       // source
    const int* col = ei + E;   // target

    // launches 0..2, then MLP at index 3 (ncu capture slot)
    cnt_zero_kernel<<<(NN + 255) / 256, 256>>>();
    cnt_acc_kernel<<<(E + 255) / 256, 256>>>(col, E);
    dinv_kernel<<<(NN + 255) / 256, 256>>>();
    mlp_kernel<<<(NN + 127) / 128, 256>>>(x, W1, b1, W2, b2);

    // CSR build
    scan1_kernel<<<NB_SCAN, 1024>>>();
    scan2_kernel<<<1, 32>>>();
    scan3_kernel<<<NB_SCAN, 1024>>>();
    fill_kernel<<<(E + 255) / 256, 256>>>(row, col, E);
    sentinel_kernel<<<2, 256>>>();

    // pull propagation: 1 warp per node, y_k history in g_yH
    int pblocks = (NN * 32 + 255) / 256;
    for (int k = 0; k < KH; k++) {
        propagate_kernel<<<pblocks, 256>>>(k);
    }

    final_kernel<<<(NN * 32 + 255) / 256, 256>>>(temp, out);
}